// round 15
// baseline (speedup 1.0000x reference)
#include <cuda_runtime.h>
#include <cuda_fp16.h>
#include <cstdint>

#define B_ 4
#define N_ 4096
#define C_ 1024
#define H_ 16
#define D_ 64
#define M_TOT (B_*N_)    // 16384
#define QKV_N (3*C_)     // 3072
#define NCHUNK 16
#define CHUNKN (N_/NCHUNK)   // 256

// ---------------- scratch (device globals; no runtime alloc) ----------------
__device__ float  g_qkv[(size_t)M_TOT * QKV_N];          // 201 MB (k,v regions used)
__device__ float  g_ctx[(size_t)B_ * H_ * D_ * D_];      // 1 MB
__device__ float  g_ctxp[NCHUNK][(size_t)B_ * H_ * D_ * D_]; // 16 MB
__device__ float  g_ctxs[NCHUNK][(size_t)B_ * H_ * D_];  // 256 KB
__device__ __half g_abuf[(size_t)M_TOT * C_];            // 32 MB (x as fp16)
__device__ __half g_qsm[(size_t)M_TOT * C_];             // 32 MB (softmaxed q, fp16)
__device__ __half g_wqkvT[(size_t)QKV_N * C_];           // 6 MB
__device__ __half g_wprojT[(size_t)C_ * C_];             // 2 MB
__device__ __half g_m2t[(size_t)B_ * C_ * C_];           // 8 MB

__device__ __forceinline__ uint32_t smem_u32(const void* p) {
    uint32_t a;
    asm("{ .reg .u64 t; cvta.to.shared.u64 t, %1; cvt.u32.u64 %0, t; }" : "=r"(a) : "l"(p));
    return a;
}

#define CP_ASYNC16(saddr, gptr) \
    asm volatile("cp.async.cg.shared.global [%0], [%1], 16;" :: "r"(saddr), "l"(gptr))
#define CP_COMMIT() asm volatile("cp.async.commit_group;" ::: "memory")
#define CP_WAIT2()  asm volatile("cp.async.wait_group 2;" ::: "memory")

#define LDMATRIX_X4(r0, r1, r2, r3, addr) \
    asm volatile("ldmatrix.sync.aligned.m8n8.x4.shared.b16 {%0, %1, %2, %3}, [%4];" \
        : "=r"(r0), "=r"(r1), "=r"(r2), "=r"(r3) : "r"(addr))

// ---- packed f32x2 (Blackwell FFMA2 path; PTX-only) ----
#define PACK2(dst, lo, hi) \
    asm("mov.b64 %0, {%1, %2};" : "=l"(dst) : "f"(lo), "f"(hi))
#define UNPACK2(lo, hi, src) \
    asm("mov.b64 {%0, %1}, %2;" : "=f"(lo), "=f"(hi) : "l"(src))
#define FMA2(d, a, b) \
    asm("fma.rn.f32x2 %0, %1, %2, %0;" : "+l"(d) : "l"(a), "l"(b))
#define ADD2(d, a) \
    asm("add.rn.f32x2 %0, %1, %0;" : "+l"(d) : "l"(a))

__device__ __forceinline__ void mma_16x8x16(
    float* c, uint32_t a0, uint32_t a1, uint32_t a2, uint32_t a3,
    uint32_t b0, uint32_t b1)
{
    asm volatile(
        "mma.sync.aligned.m16n8k16.row.col.f32.f16.f16.f32 "
        "{%0, %1, %2, %3}, {%4, %5, %6, %7}, {%8, %9}, {%0, %1, %2, %3};"
        : "+f"(c[0]), "+f"(c[1]), "+f"(c[2]), "+f"(c[3])
        : "r"(a0), "r"(a1), "r"(a2), "r"(a3), "r"(b0), "r"(b1));
}

// ---------------------------------------------------------------------------
// fp16 warp-MMA GEMM (batched, templated epilogue):
//   MODE 0: C = A @ Bt^T + bias (fp32 out)
//   MODE 1: qkv GEMM. q cols [0,C): fused softmax-over-head -> fp16 qsm.
//           k cols [C,2C): exp(val+bias) -> fp32 qkv. v: plain fp32 qkv.
// BM=128, BN=128, BK=32 halves, 4-stage cp.async, ldmatrix, 4 warps 64x64.
// ---------------------------------------------------------------------------
#define ROWB 80
#define STAGE_OP_BYTES (128 * ROWB)
#define STAGE_BYTES  (2 * STAGE_OP_BYTES)
#define GEMM_SMEM    (4 * STAGE_BYTES)

template<int MODE>
__global__ __launch_bounds__(128, 2) void gemm_mma_fp16(
    const __half* __restrict__ A, const __half* __restrict__ Bt,
    const float* __restrict__ bias, float* __restrict__ Cm,
    __half* __restrict__ qsm,
    int M, int N, int K,
    size_t aBatch, size_t bBatch, size_t cBatch)
{
    extern __shared__ char smem[];
    const uint32_t smem_base = smem_u32(smem);

    const int tid = threadIdx.x;
    const int lane = tid & 31;
    const int wid = tid >> 5;
    const int wm = (wid >> 1) * 64;
    const int wn = (wid & 1) * 64;
    const int m0 = blockIdx.y * 128, n0 = blockIdx.x * 128;
    const int z = blockIdx.z;

    const __half* Ag = A + z * aBatch + (size_t)m0 * K;
    const __half* Bg = Bt + z * bBatch + (size_t)n0 * K;
    float* Cz = Cm + z * cBatch;

    const int r0 = tid >> 2;
    const int kb = (tid & 3) * 16;
    const int kf = (tid & 3) * 8;

    const int g = lane >> 2;
    const int t4 = lane & 3;

    uint32_t a_off[4];
    #pragma unroll
    for (int mt = 0; mt < 4; mt++)
        a_off[mt] = (uint32_t)((wm + mt * 16 + (lane & 15)) * ROWB + ((lane >> 4) << 4));
    uint32_t b_off[4];
    #pragma unroll
    for (int p = 0; p < 4; p++)
        b_off[p] = (uint32_t)((wn + p * 16 + ((lane >> 4) << 3) + (lane & 7)) * ROWB
                              + (((lane >> 3) & 1) << 4) + STAGE_OP_BYTES);

    float acc[4][8][4];
    #pragma unroll
    for (int i = 0; i < 4; i++)
        #pragma unroll
        for (int j = 0; j < 8; j++)
            #pragma unroll
            for (int q = 0; q < 4; q++) acc[i][j][q] = 0.f;

    const int iters = K >> 5;

    #pragma unroll
    for (int s = 0; s < 3; s++) {
        const uint32_t sa = smem_base + s * STAGE_BYTES;
        const uint32_t sb = sa + STAGE_OP_BYTES;
        const __half* Asrc = Ag + s * 32;
        const __half* Bsrc = Bg + s * 32;
        #pragma unroll
        for (int rr = 0; rr < 4; rr++) {
            const int row = r0 + rr * 32;
            CP_ASYNC16(sa + row * ROWB + kb, Asrc + (size_t)row * K + kf);
            CP_ASYNC16(sb + row * ROWB + kb, Bsrc + (size_t)row * K + kf);
        }
        CP_COMMIT();
    }

    for (int it = 0; it < iters; it++) {
        CP_WAIT2();
        __syncthreads();

        if (it + 3 < iters) {
            const int s = (it + 3) & 3;
            const uint32_t sa = smem_base + s * STAGE_BYTES;
            const uint32_t sb = sa + STAGE_OP_BYTES;
            const __half* Asrc = Ag + (it + 3) * 32;
            const __half* Bsrc = Bg + (it + 3) * 32;
            #pragma unroll
            for (int rr = 0; rr < 4; rr++) {
                const int row = r0 + rr * 32;
                CP_ASYNC16(sa + row * ROWB + kb, Asrc + (size_t)row * K + kf);
                CP_ASYNC16(sb + row * ROWB + kb, Bsrc + (size_t)row * K + kf);
            }
        }
        CP_COMMIT();

        const uint32_t stage = smem_base + (it & 3) * STAGE_BYTES;

        #pragma unroll
        for (int s = 0; s < 2; s++) {
            const uint32_t ksb = (uint32_t)(s * 32);
            uint32_t afr[4][4];
            #pragma unroll
            for (int mt = 0; mt < 4; mt++)
                LDMATRIX_X4(afr[mt][0], afr[mt][1], afr[mt][2], afr[mt][3],
                            stage + a_off[mt] + ksb);
            uint32_t bfr[4][4];
            #pragma unroll
            for (int p = 0; p < 4; p++)
                LDMATRIX_X4(bfr[p][0], bfr[p][1], bfr[p][2], bfr[p][3],
                            stage + b_off[p] + ksb);
            #pragma unroll
            for (int nt = 0; nt < 8; nt++) {
                uint32_t b0 = bfr[nt >> 1][(nt & 1) * 2];
                uint32_t b1 = bfr[nt >> 1][(nt & 1) * 2 + 1];
                #pragma unroll
                for (int mt = 0; mt < 4; mt++)
                    mma_16x8x16(acc[mt][nt], afr[mt][0], afr[mt][1], afr[mt][2], afr[mt][3], b0, b1);
            }
        }
    }

    // -------- epilogue --------
    if (MODE == 1 && n0 < C_) {
        // q region: fused softmax over head_dim -> fp16 qsm.
        float bxv[8], byv[8];
        #pragma unroll
        for (int nt = 0; nt < 8; nt++) {
            int col = n0 + wn + nt * 8 + t4 * 2;
            bxv[nt] = bias[col];
            byv[nt] = bias[col + 1];
        }
        #pragma unroll
        for (int mt = 0; mt < 4; mt++) {
            float vt[16], vb[16];
            #pragma unroll
            for (int nt = 0; nt < 8; nt++) {
                vt[2*nt]   = acc[mt][nt][0] + bxv[nt];
                vt[2*nt+1] = acc[mt][nt][1] + byv[nt];
                vb[2*nt]   = acc[mt][nt][2] + bxv[nt];
                vb[2*nt+1] = acc[mt][nt][3] + byv[nt];
            }
            float mtv = vt[0], mbv = vb[0];
            #pragma unroll
            for (int j = 1; j < 16; j++) { mtv = fmaxf(mtv, vt[j]); mbv = fmaxf(mbv, vb[j]); }
            mtv = fmaxf(mtv, __shfl_xor_sync(0xffffffffu, mtv, 1));
            mtv = fmaxf(mtv, __shfl_xor_sync(0xffffffffu, mtv, 2));
            mbv = fmaxf(mbv, __shfl_xor_sync(0xffffffffu, mbv, 1));
            mbv = fmaxf(mbv, __shfl_xor_sync(0xffffffffu, mbv, 2));
            float st = 0.f, sb = 0.f;
            #pragma unroll
            for (int j = 0; j < 16; j++) {
                vt[j] = __expf(vt[j] - mtv); st += vt[j];
                vb[j] = __expf(vb[j] - mbv); sb += vb[j];
            }
            st += __shfl_xor_sync(0xffffffffu, st, 1);
            st += __shfl_xor_sync(0xffffffffu, st, 2);
            sb += __shfl_xor_sync(0xffffffffu, sb, 1);
            sb += __shfl_xor_sync(0xffffffffu, sb, 2);
            float it_ = 1.f / st, ib_ = 1.f / sb;
            int row = m0 + wm + mt * 16 + g;
            #pragma unroll
            for (int nt = 0; nt < 8; nt++) {
                int col = n0 + wn + nt * 8 + t4 * 2;
                __half2 ht = __floats2half2_rn(vt[2*nt] * it_, vt[2*nt+1] * it_);
                __half2 hb = __floats2half2_rn(vb[2*nt] * ib_, vb[2*nt+1] * ib_);
                *(uint32_t*)&qsm[(size_t)row * C_ + col] = *(uint32_t*)&ht;
                *(uint32_t*)&qsm[(size_t)(row + 8) * C_ + col] = *(uint32_t*)&hb;
            }
        }
    } else {
        const bool isK = (MODE == 1) && (n0 < 2 * C_);
        #pragma unroll
        for (int mt = 0; mt < 4; mt++) {
            #pragma unroll
            for (int nt = 0; nt < 8; nt++) {
                int row = m0 + wm + mt * 16 + g;
                int col = n0 + wn + nt * 8 + t4 * 2;
                float bx = bias[col], by = bias[col + 1];
                float2 o0 = {acc[mt][nt][0] + bx, acc[mt][nt][1] + by};
                float2 o1 = {acc[mt][nt][2] + bx, acc[mt][nt][3] + by};
                if (isK) {
                    o0.x = __expf(o0.x); o0.y = __expf(o0.y);
                    o1.x = __expf(o1.x); o1.y = __expf(o1.y);
                }
                *(float2*)&Cz[(size_t)row * N + col] = o0;
                *(float2*)&Cz[(size_t)(row + 8) * N + col] = o1;
            }
        }
    }
}

// ---------------------------------------------------------------------------
// W [K,N] fp32 -> Wt [N,K] fp16 transpose
// ---------------------------------------------------------------------------
__global__ void transpose_kernel(const float* __restrict__ W, __half* __restrict__ Wt,
                                 int K, int N)
{
    __shared__ float t[32][33];
    int n0 = blockIdx.x * 32, k0 = blockIdx.y * 32;
    for (int i = threadIdx.y; i < 32; i += 8)
        t[i][threadIdx.x] = W[(size_t)(k0 + i) * N + n0 + threadIdx.x];
    __syncthreads();
    for (int i = threadIdx.y; i < 32; i += 8)
        Wt[(size_t)(n0 + i) * K + k0 + threadIdx.x] = __float2half_rn(t[threadIdx.x][i]);
}

// round x -> fp16
__global__ __launch_bounds__(256) void round_x_kernel(
    const float* __restrict__ x, __half* __restrict__ xh)
{
    size_t i = ((size_t)blockIdx.x * 256 + threadIdx.x) * 4;
    float4 v = *(const float4*)(x + i);
    __half2 h0 = __floats2half2_rn(v.x, v.y);
    __half2 h1 = __floats2half2_rn(v.z, v.w);
    uint2 o = {*(uint32_t*)&h0, *(uint32_t*)&h1};
    *(uint2*)(xh + i) = o;
}

// ---------------------------------------------------------------------------
// ctx partial: k region already holds exp(k). Accumulate ek^T v + colsums.
// Inner loop on packed f32x2 (FFMA2) — FMA-pipe ops halved.
// ---------------------------------------------------------------------------
__global__ __launch_bounds__(256) void ctx_partial_kernel(
    const float* __restrict__ qkv, float* __restrict__ ctxp, float* __restrict__ ctxs)
{
    int bh = blockIdx.x;
    int chunk = blockIdx.y;
    int b = bh >> 4, h = bh & 15;
    const float* kbase = qkv + (size_t)b * N_ * QKV_N + C_     + h * D_;
    const float* vbase = qkv + (size_t)b * N_ * QKV_N + 2 * C_ + h * D_;

    __shared__ float Ks[32][64];
    __shared__ float Vs[32][64];

    int tid = threadIdx.x;
    int tx = tid & 15, ty = tid >> 4;
    int ln = tid >> 3;
    int ld = (tid & 7) * 8;

    uint64_t acc2[4][2];     // acc2[i][j2]: e pair (2*j2, 2*j2+1) for d = ty*4+i
    uint64_t accs2[2];       // colsum pairs: d (ty*4+0,1), (ty*4+2,3)
    #pragma unroll
    for (int i = 0; i < 4; i++) { acc2[i][0] = 0ull; acc2[i][1] = 0ull; }
    accs2[0] = 0ull; accs2[1] = 0ull;

    int nbeg = chunk * CHUNKN, nend = nbeg + CHUNKN;
    for (int nt = nbeg; nt < nend; nt += 32) {
        const float* kp = kbase + (size_t)(nt + ln) * QKV_N + ld;
        const float* vp = vbase + (size_t)(nt + ln) * QKV_N + ld;
        float4 k0 = *(const float4*)kp;
        float4 k1 = *(const float4*)(kp + 4);
        float4 v0 = *(const float4*)vp;
        float4 v1 = *(const float4*)(vp + 4);
        __syncthreads();
        *(float4*)&Ks[ln][ld]     = k0;
        *(float4*)&Ks[ln][ld + 4] = k1;
        *(float4*)&Vs[ln][ld]     = v0;
        *(float4*)&Vs[ln][ld + 4] = v1;
        __syncthreads();

        #pragma unroll 8
        for (int n = 0; n < 32; n++) {
            float4 a = *(float4*)&Ks[n][ty * 4];
            float4 v = *(float4*)&Vs[n][tx * 4];
            uint64_t bp0, bp1, ap0, ap1;
            PACK2(bp0, v.x, v.y);
            PACK2(bp1, v.z, v.w);
            PACK2(ap0, a.x, a.y);
            PACK2(ap1, a.z, a.w);
            ADD2(accs2[0], ap0);
            ADD2(accs2[1], ap1);
            float av[4] = {a.x, a.y, a.z, a.w};
            #pragma unroll
            for (int i = 0; i < 4; i++) {
                uint64_t ai;
                PACK2(ai, av[i], av[i]);
                FMA2(acc2[i][0], ai, bp0);
                FMA2(acc2[i][1], ai, bp1);
            }
        }
    }

    float* cp = ctxp + ((size_t)chunk * (B_ * H_) + bh) * D_ * D_;
    #pragma unroll
    for (int i = 0; i < 4; i++) {
        float4 o;
        UNPACK2(o.x, o.y, acc2[i][0]);
        UNPACK2(o.z, o.w, acc2[i][1]);
        *(float4*)&cp[(ty * 4 + i) * D_ + tx * 4] = o;
    }
    if (tx == 0) {
        float s0, s1, s2, s3;
        UNPACK2(s0, s1, accs2[0]);
        UNPACK2(s2, s3, accs2[1]);
        float* sp = ctxs + (size_t)chunk * (B_ * H_ * D_) + bh * D_;
        sp[ty * 4 + 0] = s0;
        sp[ty * 4 + 1] = s1;
        sp[ty * 4 + 2] = s2;
        sp[ty * 4 + 3] = s3;
    }
}

__global__ __launch_bounds__(256) void ctx_reduce_kernel(
    const float* __restrict__ ctxp, const float* __restrict__ ctxs,
    float* __restrict__ ctx)
{
    int idx = blockIdx.x * 256 + threadIdx.x;
    const int total = B_ * H_ * D_ * D_;
    if (idx >= total) return;
    int bh = idx >> 12;
    int d  = (idx >> 6) & 63;
    float s = 0.f, se = 0.f;
    #pragma unroll
    for (int c = 0; c < NCHUNK; c++) {
        s  += ctxp[(size_t)c * total + idx];
        se += ctxs[(size_t)c * (B_ * H_ * D_) + bh * D_ + d];
    }
    ctx[idx] = s / se;
}

// ---------------------------------------------------------------------------
// M2t[b][c, h*64+d] = sum_e ctx[b,h,d,e] * wprojT[c, h*64+e]   (fp16 out)
// Dot products on packed f32x2.
// ---------------------------------------------------------------------------
__global__ __launch_bounds__(256) void m2_kernel(
    const float* __restrict__ ctx, const __half* __restrict__ wprojT,
    __half* __restrict__ m2t)
{
    int b = blockIdx.z, h = blockIdx.y, cc = blockIdx.x;
    __shared__ float cs[64 * 64];

    const float* cp = ctx + (size_t)(b * H_ + h) * D_ * D_;
    for (int i = threadIdx.x * 4; i < 4096; i += 1024)
        *(float4*)&cs[i] = *(const float4*)&cp[i];
    __syncthreads();

    int c = cc * 128 + (threadIdx.x >> 1);
    int d0 = (threadIdx.x & 1) * 32;

    uint64_t w2[32];
    const __half2* wp = (const __half2*)(wprojT + (size_t)c * C_ + h * 64);
    #pragma unroll
    for (int e = 0; e < 32; e++) {
        float2 f = __half22float2(wp[e]);
        PACK2(w2[e], f.x, f.y);
    }

    float acc[32];
    #pragma unroll
    for (int i = 0; i < 32; i++) {
        const uint64_t* rowp = (const uint64_t*)(cs + (d0 + i) * 64);
        uint64_t a2 = 0ull;
        #pragma unroll
        for (int e2 = 0; e2 < 32; e2++)
            FMA2(a2, rowp[e2], w2[e2]);
        float lo, hi;
        UNPACK2(lo, hi, a2);
        acc[i] = lo + hi;
    }

    uint32_t pk[16];
    #pragma unroll
    for (int j = 0; j < 16; j++) {
        __half2 hh = __floats2half2_rn(acc[2*j], acc[2*j+1]);
        pk[j] = *(uint32_t*)&hh;
    }
    __half* op = m2t + (size_t)b * C_ * C_ + (size_t)c * C_ + h * 64 + d0;
    #pragma unroll
    for (int j = 0; j < 4; j++) {
        uint4 o = {pk[4*j], pk[4*j+1], pk[4*j+2], pk[4*j+3]};
        *(uint4*)(op + j * 8) = o;
    }
}

// ---------------------------------------------------------------------------
extern "C" void kernel_launch(void* const* d_in, const int* in_sizes, int n_in,
                              void* d_out, int out_size)
{
    (void)in_sizes; (void)n_in; (void)out_size;
    const float* x     = (const float*)d_in[0];
    const float* Wqkv  = (const float*)d_in[1];
    const float* bqkv  = (const float*)d_in[2];
    const float* Wproj = (const float*)d_in[3];
    const float* bproj = (const float*)d_in[4];
    float* out = (float*)d_out;

    float *qkv, *ctx, *ctxp, *ctxs;
    __half *abuf, *qsm, *wqkvT, *wprojT, *m2t;
    cudaGetSymbolAddress((void**)&qkv,    g_qkv);
    cudaGetSymbolAddress((void**)&ctx,    g_ctx);
    cudaGetSymbolAddress((void**)&ctxp,   g_ctxp);
    cudaGetSymbolAddress((void**)&ctxs,   g_ctxs);
    cudaGetSymbolAddress((void**)&abuf,   g_abuf);
    cudaGetSymbolAddress((void**)&qsm,    g_qsm);
    cudaGetSymbolAddress((void**)&wqkvT,  g_wqkvT);
    cudaGetSymbolAddress((void**)&wprojT, g_wprojT);
    cudaGetSymbolAddress((void**)&m2t,    g_m2t);

    cudaFuncSetAttribute(gemm_mma_fp16<0>,
                         cudaFuncAttributeMaxDynamicSharedMemorySize, GEMM_SMEM);
    cudaFuncSetAttribute(gemm_mma_fp16<1>,
                         cudaFuncAttributeMaxDynamicSharedMemorySize, GEMM_SMEM);

    // 0) x -> fp16; weights -> [N,K] fp16
    round_x_kernel<<<M_TOT * C_ / 1024, 256>>>(x, abuf);
    transpose_kernel<<<dim3(QKV_N / 32, C_ / 32), dim3(32, 8)>>>(Wqkv, wqkvT, C_, QKV_N);
    transpose_kernel<<<dim3(C_ / 32, C_ / 32), dim3(32, 8)>>>(Wproj, wprojT, C_, C_);

    // 1) qkv GEMM, fused epilogue: q -> per-head softmax -> fp16 g_qsm;
    //    k -> exp(k+bias) fp32 in qkv; v -> plain fp32 in qkv.
    gemm_mma_fp16<1><<<dim3(QKV_N / 128, M_TOT / 128, 1), 128, GEMM_SMEM>>>(
        abuf, wqkvT, bqkv, qkv, qsm, M_TOT, QKV_N, C_, 0, 0, 0);

    // 2) context = softmax_N(k)^T v  (k region already exp'd; colsum-normalized)
    ctx_partial_kernel<<<dim3(B_ * H_, NCHUNK), 256>>>(qkv, ctxp, ctxs);
    ctx_reduce_kernel<<<(B_ * H_ * D_ * D_ + 255) / 256, 256>>>(ctxp, ctxs, ctx);

    // 3) M2t[b] = (ctx @ Wproj_head)^T fp16
    m2_kernel<<<dim3(8, H_, B_), 256>>>(ctx, wprojT, m2t);

    // 4) out[b] = q_sm[b] @ M2t[b]^T + bproj   (batched fp16 MMA GEMM)
    gemm_mma_fp16<0><<<dim3(C_ / 128, N_ / 128, B_), 128, GEMM_SMEM>>>(
        qsm, m2t, bproj, out, nullptr, N_, C_, C_,
        (size_t)N_ * C_, (size_t)C_ * C_, (size_t)N_ * C_);
}

// round 16
// speedup vs baseline: 1.0121x; 1.0121x over previous
#include <cuda_runtime.h>
#include <cuda_fp16.h>
#include <cstdint>

#define B_ 4
#define N_ 4096
#define C_ 1024
#define H_ 16
#define D_ 64
#define M_TOT (B_*N_)    // 16384
#define QKV_N (3*C_)     // 3072
#define NCHUNK 16
#define CHUNKN (N_/NCHUNK)   // 256

// ---------------- scratch (device globals; no runtime alloc) ----------------
__device__ float  g_ctx[(size_t)B_ * H_ * D_ * D_];      // 1 MB
__device__ float  g_ctxp[NCHUNK][(size_t)B_ * H_ * D_ * D_]; // 16 MB
__device__ float  g_ctxs[NCHUNK][(size_t)B_ * H_ * D_];  // 256 KB
__device__ __half g_abuf[(size_t)M_TOT * C_];            // 32 MB (x as fp16)
__device__ __half g_qsm[(size_t)M_TOT * C_];             // 32 MB (softmaxed q)
__device__ __half g_kh[(size_t)M_TOT * C_];              // 32 MB (exp(k) fp16)
__device__ __half g_vh[(size_t)M_TOT * C_];              // 32 MB (v fp16)
__device__ __half g_wqkvT[(size_t)QKV_N * C_];           // 6 MB
__device__ __half g_wprojT[(size_t)C_ * C_];             // 2 MB
__device__ __half g_m2t[(size_t)B_ * C_ * C_];           // 8 MB

__device__ __forceinline__ uint32_t smem_u32(const void* p) {
    uint32_t a;
    asm("{ .reg .u64 t; cvta.to.shared.u64 t, %1; cvt.u32.u64 %0, t; }" : "=r"(a) : "l"(p));
    return a;
}

#define CP_ASYNC16(saddr, gptr) \
    asm volatile("cp.async.cg.shared.global [%0], [%1], 16;" :: "r"(saddr), "l"(gptr))
#define CP_COMMIT() asm volatile("cp.async.commit_group;" ::: "memory")
#define CP_WAIT2()  asm volatile("cp.async.wait_group 2;" ::: "memory")

#define LDMATRIX_X4(r0, r1, r2, r3, addr) \
    asm volatile("ldmatrix.sync.aligned.m8n8.x4.shared.b16 {%0, %1, %2, %3}, [%4];" \
        : "=r"(r0), "=r"(r1), "=r"(r2), "=r"(r3) : "r"(addr))

// ---- packed f32x2 (Blackwell FFMA2; PTX-only) ----
#define PACK2(dst, lo, hi) \
    asm("mov.b64 %0, {%1, %2};" : "=l"(dst) : "f"(lo), "f"(hi))
#define UNPACK2(lo, hi, src) \
    asm("mov.b64 {%0, %1}, %2;" : "=f"(lo), "=f"(hi) : "l"(src))
#define FMA2(d, a, b) \
    asm("fma.rn.f32x2 %0, %1, %2, %0;" : "+l"(d) : "l"(a), "l"(b))
#define ADD2(d, a) \
    asm("add.rn.f32x2 %0, %1, %0;" : "+l"(d) : "l"(a))

__device__ __forceinline__ void mma_16x8x16(
    float* c, uint32_t a0, uint32_t a1, uint32_t a2, uint32_t a3,
    uint32_t b0, uint32_t b1)
{
    asm volatile(
        "mma.sync.aligned.m16n8k16.row.col.f32.f16.f16.f32 "
        "{%0, %1, %2, %3}, {%4, %5, %6, %7}, {%8, %9}, {%0, %1, %2, %3};"
        : "+f"(c[0]), "+f"(c[1]), "+f"(c[2]), "+f"(c[3])
        : "r"(a0), "r"(a1), "r"(a2), "r"(a3), "r"(b0), "r"(b1));
}

// ---------------------------------------------------------------------------
// fp16 warp-MMA GEMM (batched, templated epilogue):
//   MODE 0: C = A @ Bt^T + bias (fp32 out)
//   MODE 1: qkv GEMM, all-fp16 outputs:
//     q cols [0,C):   fused softmax-over-head -> qsm   (row*C + col)
//     k cols [C,2C):  exp(val+bias) fp16     -> kh    (row*C + col-C)
//     v cols [2C,3C): fp16                    -> vh    (row*C + col-2C)
// BM=128, BN=128, BK=32 halves, 4-stage cp.async, ldmatrix, 4 warps 64x64.
// ---------------------------------------------------------------------------
#define ROWB 80
#define STAGE_OP_BYTES (128 * ROWB)
#define STAGE_BYTES  (2 * STAGE_OP_BYTES)
#define GEMM_SMEM    (4 * STAGE_BYTES)

template<int MODE>
__global__ __launch_bounds__(128, 2) void gemm_mma_fp16(
    const __half* __restrict__ A, const __half* __restrict__ Bt,
    const float* __restrict__ bias, float* __restrict__ Cm,
    __half* __restrict__ qsm, __half* __restrict__ kh, __half* __restrict__ vh,
    int M, int N, int K,
    size_t aBatch, size_t bBatch, size_t cBatch)
{
    extern __shared__ char smem[];
    const uint32_t smem_base = smem_u32(smem);

    const int tid = threadIdx.x;
    const int lane = tid & 31;
    const int wid = tid >> 5;
    const int wm = (wid >> 1) * 64;
    const int wn = (wid & 1) * 64;
    const int m0 = blockIdx.y * 128, n0 = blockIdx.x * 128;
    const int z = blockIdx.z;

    const __half* Ag = A + z * aBatch + (size_t)m0 * K;
    const __half* Bg = Bt + z * bBatch + (size_t)n0 * K;
    float* Cz = Cm + z * cBatch;

    const int r0 = tid >> 2;
    const int kb = (tid & 3) * 16;
    const int kf = (tid & 3) * 8;

    const int g = lane >> 2;
    const int t4 = lane & 3;

    uint32_t a_off[4];
    #pragma unroll
    for (int mt = 0; mt < 4; mt++)
        a_off[mt] = (uint32_t)((wm + mt * 16 + (lane & 15)) * ROWB + ((lane >> 4) << 4));
    uint32_t b_off[4];
    #pragma unroll
    for (int p = 0; p < 4; p++)
        b_off[p] = (uint32_t)((wn + p * 16 + ((lane >> 4) << 3) + (lane & 7)) * ROWB
                              + (((lane >> 3) & 1) << 4) + STAGE_OP_BYTES);

    float acc[4][8][4];
    #pragma unroll
    for (int i = 0; i < 4; i++)
        #pragma unroll
        for (int j = 0; j < 8; j++)
            #pragma unroll
            for (int q = 0; q < 4; q++) acc[i][j][q] = 0.f;

    const int iters = K >> 5;

    #pragma unroll
    for (int s = 0; s < 3; s++) {
        const uint32_t sa = smem_base + s * STAGE_BYTES;
        const uint32_t sb = sa + STAGE_OP_BYTES;
        const __half* Asrc = Ag + s * 32;
        const __half* Bsrc = Bg + s * 32;
        #pragma unroll
        for (int rr = 0; rr < 4; rr++) {
            const int row = r0 + rr * 32;
            CP_ASYNC16(sa + row * ROWB + kb, Asrc + (size_t)row * K + kf);
            CP_ASYNC16(sb + row * ROWB + kb, Bsrc + (size_t)row * K + kf);
        }
        CP_COMMIT();
    }

    for (int it = 0; it < iters; it++) {
        CP_WAIT2();
        __syncthreads();

        if (it + 3 < iters) {
            const int s = (it + 3) & 3;
            const uint32_t sa = smem_base + s * STAGE_BYTES;
            const uint32_t sb = sa + STAGE_OP_BYTES;
            const __half* Asrc = Ag + (it + 3) * 32;
            const __half* Bsrc = Bg + (it + 3) * 32;
            #pragma unroll
            for (int rr = 0; rr < 4; rr++) {
                const int row = r0 + rr * 32;
                CP_ASYNC16(sa + row * ROWB + kb, Asrc + (size_t)row * K + kf);
                CP_ASYNC16(sb + row * ROWB + kb, Bsrc + (size_t)row * K + kf);
            }
        }
        CP_COMMIT();

        const uint32_t stage = smem_base + (it & 3) * STAGE_BYTES;

        #pragma unroll
        for (int s = 0; s < 2; s++) {
            const uint32_t ksb = (uint32_t)(s * 32);
            uint32_t afr[4][4];
            #pragma unroll
            for (int mt = 0; mt < 4; mt++)
                LDMATRIX_X4(afr[mt][0], afr[mt][1], afr[mt][2], afr[mt][3],
                            stage + a_off[mt] + ksb);
            uint32_t bfr[4][4];
            #pragma unroll
            for (int p = 0; p < 4; p++)
                LDMATRIX_X4(bfr[p][0], bfr[p][1], bfr[p][2], bfr[p][3],
                            stage + b_off[p] + ksb);
            #pragma unroll
            for (int nt = 0; nt < 8; nt++) {
                uint32_t b0 = bfr[nt >> 1][(nt & 1) * 2];
                uint32_t b1 = bfr[nt >> 1][(nt & 1) * 2 + 1];
                #pragma unroll
                for (int mt = 0; mt < 4; mt++)
                    mma_16x8x16(acc[mt][nt], afr[mt][0], afr[mt][1], afr[mt][2], afr[mt][3], b0, b1);
            }
        }
    }

    // -------- epilogue --------
    if (MODE == 1 && n0 < C_) {
        // q: fused softmax over head -> fp16 qsm
        float bxv[8], byv[8];
        #pragma unroll
        for (int nt = 0; nt < 8; nt++) {
            int col = n0 + wn + nt * 8 + t4 * 2;
            bxv[nt] = bias[col];
            byv[nt] = bias[col + 1];
        }
        #pragma unroll
        for (int mt = 0; mt < 4; mt++) {
            float vt[16], vb[16];
            #pragma unroll
            for (int nt = 0; nt < 8; nt++) {
                vt[2*nt]   = acc[mt][nt][0] + bxv[nt];
                vt[2*nt+1] = acc[mt][nt][1] + byv[nt];
                vb[2*nt]   = acc[mt][nt][2] + bxv[nt];
                vb[2*nt+1] = acc[mt][nt][3] + byv[nt];
            }
            float mtv = vt[0], mbv = vb[0];
            #pragma unroll
            for (int j = 1; j < 16; j++) { mtv = fmaxf(mtv, vt[j]); mbv = fmaxf(mbv, vb[j]); }
            mtv = fmaxf(mtv, __shfl_xor_sync(0xffffffffu, mtv, 1));
            mtv = fmaxf(mtv, __shfl_xor_sync(0xffffffffu, mtv, 2));
            mbv = fmaxf(mbv, __shfl_xor_sync(0xffffffffu, mbv, 1));
            mbv = fmaxf(mbv, __shfl_xor_sync(0xffffffffu, mbv, 2));
            float st = 0.f, sb = 0.f;
            #pragma unroll
            for (int j = 0; j < 16; j++) {
                vt[j] = __expf(vt[j] - mtv); st += vt[j];
                vb[j] = __expf(vb[j] - mbv); sb += vb[j];
            }
            st += __shfl_xor_sync(0xffffffffu, st, 1);
            st += __shfl_xor_sync(0xffffffffu, st, 2);
            sb += __shfl_xor_sync(0xffffffffu, sb, 1);
            sb += __shfl_xor_sync(0xffffffffu, sb, 2);
            float it_ = 1.f / st, ib_ = 1.f / sb;
            int row = m0 + wm + mt * 16 + g;
            #pragma unroll
            for (int nt = 0; nt < 8; nt++) {
                int col = n0 + wn + nt * 8 + t4 * 2;
                __half2 ht = __floats2half2_rn(vt[2*nt] * it_, vt[2*nt+1] * it_);
                __half2 hb = __floats2half2_rn(vb[2*nt] * ib_, vb[2*nt+1] * ib_);
                *(uint32_t*)&qsm[(size_t)row * C_ + col] = *(uint32_t*)&ht;
                *(uint32_t*)&qsm[(size_t)(row + 8) * C_ + col] = *(uint32_t*)&hb;
            }
        }
    } else if (MODE == 1) {
        // k region -> exp fp16 kh; v region -> fp16 vh
        const bool isK = (n0 < 2 * C_);
        __half* dst = isK ? kh : vh;
        const int cbase = n0 - (isK ? C_ : 2 * C_);
        #pragma unroll
        for (int mt = 0; mt < 4; mt++) {
            #pragma unroll
            for (int nt = 0; nt < 8; nt++) {
                int row = m0 + wm + mt * 16 + g;
                int col = n0 + wn + nt * 8 + t4 * 2;
                int oc  = cbase + wn + nt * 8 + t4 * 2;
                float bx = bias[col], by = bias[col + 1];
                float2 o0 = {acc[mt][nt][0] + bx, acc[mt][nt][1] + by};
                float2 o1 = {acc[mt][nt][2] + bx, acc[mt][nt][3] + by};
                if (isK) {
                    o0.x = __expf(o0.x); o0.y = __expf(o0.y);
                    o1.x = __expf(o1.x); o1.y = __expf(o1.y);
                }
                __half2 h0 = __floats2half2_rn(o0.x, o0.y);
                __half2 h1 = __floats2half2_rn(o1.x, o1.y);
                *(uint32_t*)&dst[(size_t)row * C_ + oc] = *(uint32_t*)&h0;
                *(uint32_t*)&dst[(size_t)(row + 8) * C_ + oc] = *(uint32_t*)&h1;
            }
        }
    } else {
        #pragma unroll
        for (int mt = 0; mt < 4; mt++) {
            #pragma unroll
            for (int nt = 0; nt < 8; nt++) {
                int row = m0 + wm + mt * 16 + g;
                int col = n0 + wn + nt * 8 + t4 * 2;
                float bx = bias[col], by = bias[col + 1];
                float2 o0 = {acc[mt][nt][0] + bx, acc[mt][nt][1] + by};
                float2 o1 = {acc[mt][nt][2] + bx, acc[mt][nt][3] + by};
                *(float2*)&Cz[(size_t)row * N + col] = o0;
                *(float2*)&Cz[(size_t)(row + 8) * N + col] = o1;
            }
        }
    }
}

// ---------------------------------------------------------------------------
// W [K,N] fp32 -> Wt [N,K] fp16 transpose
// ---------------------------------------------------------------------------
__global__ void transpose_kernel(const float* __restrict__ W, __half* __restrict__ Wt,
                                 int K, int N)
{
    __shared__ float t[32][33];
    int n0 = blockIdx.x * 32, k0 = blockIdx.y * 32;
    for (int i = threadIdx.y; i < 32; i += 8)
        t[i][threadIdx.x] = W[(size_t)(k0 + i) * N + n0 + threadIdx.x];
    __syncthreads();
    for (int i = threadIdx.y; i < 32; i += 8)
        Wt[(size_t)(n0 + i) * K + k0 + threadIdx.x] = __float2half_rn(t[threadIdx.x][i]);
}

// round x -> fp16
__global__ __launch_bounds__(256) void round_x_kernel(
    const float* __restrict__ x, __half* __restrict__ xh)
{
    size_t i = ((size_t)blockIdx.x * 256 + threadIdx.x) * 4;
    float4 v = *(const float4*)(x + i);
    __half2 h0 = __floats2half2_rn(v.x, v.y);
    __half2 h1 = __floats2half2_rn(v.z, v.w);
    uint2 o = {*(uint32_t*)&h0, *(uint32_t*)&h1};
    *(uint2*)(xh + i) = o;
}

// ---------------------------------------------------------------------------
// ctx partial: kh holds exp(k) fp16, vh holds v fp16 (layout row*C + h*64+d).
// Accumulate ek^T v (fp32 FFMA2) + per-d colsums.
// ---------------------------------------------------------------------------
__global__ __launch_bounds__(256) void ctx_partial_kernel(
    const __half* __restrict__ kh, const __half* __restrict__ vh,
    float* __restrict__ ctxp, float* __restrict__ ctxs)
{
    int bh = blockIdx.x;
    int chunk = blockIdx.y;
    int b = bh >> 4, h = bh & 15;
    const __half* kbase = kh + (size_t)b * N_ * C_ + h * D_;
    const __half* vbase = vh + (size_t)b * N_ * C_ + h * D_;

    __shared__ float Ks[32][64];
    __shared__ float Vs[32][64];

    int tid = threadIdx.x;
    int tx = tid & 15, ty = tid >> 4;
    int ln = tid >> 3;
    int ld = (tid & 7) * 8;

    uint64_t acc2[4][2];
    uint64_t accs2[2];
    #pragma unroll
    for (int i = 0; i < 4; i++) { acc2[i][0] = 0ull; acc2[i][1] = 0ull; }
    accs2[0] = 0ull; accs2[1] = 0ull;

    int nbeg = chunk * CHUNKN, nend = nbeg + CHUNKN;
    for (int nt = nbeg; nt < nend; nt += 32) {
        const __half* kp = kbase + (size_t)(nt + ln) * C_ + ld;
        const __half* vp = vbase + (size_t)(nt + ln) * C_ + ld;
        uint4 kr = *(const uint4*)kp;    // 8 halves
        uint4 vr = *(const uint4*)vp;
        const __half2* k2 = (const __half2*)&kr;
        const __half2* v2 = (const __half2*)&vr;
        float2 kf0 = __half22float2(k2[0]), kf1 = __half22float2(k2[1]);
        float2 kf2 = __half22float2(k2[2]), kf3 = __half22float2(k2[3]);
        float2 vf0 = __half22float2(v2[0]), vf1 = __half22float2(v2[1]);
        float2 vf2 = __half22float2(v2[2]), vf3 = __half22float2(v2[3]);
        __syncthreads();
        *(float4*)&Ks[ln][ld]     = make_float4(kf0.x, kf0.y, kf1.x, kf1.y);
        *(float4*)&Ks[ln][ld + 4] = make_float4(kf2.x, kf2.y, kf3.x, kf3.y);
        *(float4*)&Vs[ln][ld]     = make_float4(vf0.x, vf0.y, vf1.x, vf1.y);
        *(float4*)&Vs[ln][ld + 4] = make_float4(vf2.x, vf2.y, vf3.x, vf3.y);
        __syncthreads();

        #pragma unroll 8
        for (int n = 0; n < 32; n++) {
            float4 a = *(float4*)&Ks[n][ty * 4];
            float4 v = *(float4*)&Vs[n][tx * 4];
            uint64_t bp0, bp1, ap0, ap1;
            PACK2(bp0, v.x, v.y);
            PACK2(bp1, v.z, v.w);
            PACK2(ap0, a.x, a.y);
            PACK2(ap1, a.z, a.w);
            ADD2(accs2[0], ap0);
            ADD2(accs2[1], ap1);
            float av[4] = {a.x, a.y, a.z, a.w};
            #pragma unroll
            for (int i = 0; i < 4; i++) {
                uint64_t ai;
                PACK2(ai, av[i], av[i]);
                FMA2(acc2[i][0], ai, bp0);
                FMA2(acc2[i][1], ai, bp1);
            }
        }
    }

    float* cp = ctxp + ((size_t)chunk * (B_ * H_) + bh) * D_ * D_;
    #pragma unroll
    for (int i = 0; i < 4; i++) {
        float4 o;
        UNPACK2(o.x, o.y, acc2[i][0]);
        UNPACK2(o.z, o.w, acc2[i][1]);
        *(float4*)&cp[(ty * 4 + i) * D_ + tx * 4] = o;
    }
    if (tx == 0) {
        float s0, s1, s2, s3;
        UNPACK2(s0, s1, accs2[0]);
        UNPACK2(s2, s3, accs2[1]);
        float* sp = ctxs + (size_t)chunk * (B_ * H_ * D_) + bh * D_;
        sp[ty * 4 + 0] = s0;
        sp[ty * 4 + 1] = s1;
        sp[ty * 4 + 2] = s2;
        sp[ty * 4 + 3] = s3;
    }
}

__global__ __launch_bounds__(256) void ctx_reduce_kernel(
    const float* __restrict__ ctxp, const float* __restrict__ ctxs,
    float* __restrict__ ctx)
{
    int idx = blockIdx.x * 256 + threadIdx.x;
    const int total = B_ * H_ * D_ * D_;
    if (idx >= total) return;
    int bh = idx >> 12;
    int d  = (idx >> 6) & 63;
    float s = 0.f, se = 0.f;
    #pragma unroll
    for (int c = 0; c < NCHUNK; c++) {
        s  += ctxp[(size_t)c * total + idx];
        se += ctxs[(size_t)c * (B_ * H_ * D_) + bh * D_ + d];
    }
    ctx[idx] = s / se;
}

// ---------------------------------------------------------------------------
// M2t[b][c, h*64+d] = sum_e ctx[b,h,d,e] * wprojT[c, h*64+e]   (fp16 out)
// ---------------------------------------------------------------------------
__global__ __launch_bounds__(256) void m2_kernel(
    const float* __restrict__ ctx, const __half* __restrict__ wprojT,
    __half* __restrict__ m2t)
{
    int b = blockIdx.z, h = blockIdx.y, cc = blockIdx.x;
    __shared__ float cs[64 * 64];

    const float* cp = ctx + (size_t)(b * H_ + h) * D_ * D_;
    for (int i = threadIdx.x * 4; i < 4096; i += 1024)
        *(float4*)&cs[i] = *(const float4*)&cp[i];
    __syncthreads();

    int c = cc * 128 + (threadIdx.x >> 1);
    int d0 = (threadIdx.x & 1) * 32;

    uint64_t w2[32];
    const __half2* wp = (const __half2*)(wprojT + (size_t)c * C_ + h * 64);
    #pragma unroll
    for (int e = 0; e < 32; e++) {
        float2 f = __half22float2(wp[e]);
        PACK2(w2[e], f.x, f.y);
    }

    float acc[32];
    #pragma unroll
    for (int i = 0; i < 32; i++) {
        const uint64_t* rowp = (const uint64_t*)(cs + (d0 + i) * 64);
        uint64_t a2 = 0ull;
        #pragma unroll
        for (int e2 = 0; e2 < 32; e2++)
            FMA2(a2, rowp[e2], w2[e2]);
        float lo, hi;
        UNPACK2(lo, hi, a2);
        acc[i] = lo + hi;
    }

    uint32_t pk[16];
    #pragma unroll
    for (int j = 0; j < 16; j++) {
        __half2 hh = __floats2half2_rn(acc[2*j], acc[2*j+1]);
        pk[j] = *(uint32_t*)&hh;
    }
    __half* op = m2t + (size_t)b * C_ * C_ + (size_t)c * C_ + h * 64 + d0;
    #pragma unroll
    for (int j = 0; j < 4; j++) {
        uint4 o = {pk[4*j], pk[4*j+1], pk[4*j+2], pk[4*j+3]};
        *(uint4*)(op + j * 8) = o;
    }
}

// ---------------------------------------------------------------------------
extern "C" void kernel_launch(void* const* d_in, const int* in_sizes, int n_in,
                              void* d_out, int out_size)
{
    (void)in_sizes; (void)n_in; (void)out_size;
    const float* x     = (const float*)d_in[0];
    const float* Wqkv  = (const float*)d_in[1];
    const float* bqkv  = (const float*)d_in[2];
    const float* Wproj = (const float*)d_in[3];
    const float* bproj = (const float*)d_in[4];
    float* out = (float*)d_out;

    float *ctx, *ctxp, *ctxs;
    __half *abuf, *qsm, *kh, *vh, *wqkvT, *wprojT, *m2t;
    cudaGetSymbolAddress((void**)&ctx,    g_ctx);
    cudaGetSymbolAddress((void**)&ctxp,   g_ctxp);
    cudaGetSymbolAddress((void**)&ctxs,   g_ctxs);
    cudaGetSymbolAddress((void**)&abuf,   g_abuf);
    cudaGetSymbolAddress((void**)&qsm,    g_qsm);
    cudaGetSymbolAddress((void**)&kh,     g_kh);
    cudaGetSymbolAddress((void**)&vh,     g_vh);
    cudaGetSymbolAddress((void**)&wqkvT,  g_wqkvT);
    cudaGetSymbolAddress((void**)&wprojT, g_wprojT);
    cudaGetSymbolAddress((void**)&m2t,    g_m2t);

    cudaFuncSetAttribute(gemm_mma_fp16<0>,
                         cudaFuncAttributeMaxDynamicSharedMemorySize, GEMM_SMEM);
    cudaFuncSetAttribute(gemm_mma_fp16<1>,
                         cudaFuncAttributeMaxDynamicSharedMemorySize, GEMM_SMEM);

    // 0) x -> fp16; weights -> [N,K] fp16
    round_x_kernel<<<M_TOT * C_ / 1024, 256>>>(x, abuf);
    transpose_kernel<<<dim3(QKV_N / 32, C_ / 32), dim3(32, 8)>>>(Wqkv, wqkvT, C_, QKV_N);
    transpose_kernel<<<dim3(C_ / 32, C_ / 32), dim3(32, 8)>>>(Wproj, wprojT, C_, C_);

    // 1) qkv GEMM, fused epilogue: q->softmax fp16 qsm; k->exp fp16 kh; v->fp16 vh
    gemm_mma_fp16<1><<<dim3(QKV_N / 128, M_TOT / 128, 1), 128, GEMM_SMEM>>>(
        abuf, wqkvT, bqkv, nullptr, qsm, kh, vh, M_TOT, QKV_N, C_, 0, 0, 0);

    // 2) context = softmax_N(k)^T v  (fp16 inputs, fp32 accum, colsum-normalized)
    ctx_partial_kernel<<<dim3(B_ * H_, NCHUNK), 256>>>(kh, vh, ctxp, ctxs);
    ctx_reduce_kernel<<<(B_ * H_ * D_ * D_ + 255) / 256, 256>>>(ctxp, ctxs, ctx);

    // 3) M2t[b] = (ctx @ Wproj_head)^T fp16
    m2_kernel<<<dim3(8, H_, B_), 256>>>(ctx, wprojT, m2t);

    // 4) out[b] = q_sm[b] @ M2t[b]^T + bproj   (batched fp16 MMA GEMM)
    gemm_mma_fp16<0><<<dim3(C_ / 128, N_ / 128, B_), 128, GEMM_SMEM>>>(
        qsm, m2t, bproj, out, nullptr, nullptr, nullptr, N_, C_, C_,
        (size_t)N_ * C_, (size_t)C_ * C_, (size_t)N_ * C_);
}